// round 3
// baseline (speedup 1.0000x reference)
#include <cuda_runtime.h>
#include <math_constants.h>

// RandomFeatures: lane = batch layout.
// One warp per kernel k; xs holds x transposed [T][32(+pad)] in shared so that
// xs[idx*33 + lane] is lane-consecutive (conflict-free) and idx is warp-uniform.
// Per residue r (p = r + m*d) the dilated conv is a stride-1 sliding window in
// m: load NB+KLEN-1 values per NB outputs -> ~0.17 loads/tap, zero conflicts.
// Each lane owns one batch => no final cross-lane reduction.

#define MAX_KLEN 11
#define NB 8
#define WARPS_PER_CTA 10
#define XPITCH 33

template<int KLEN>
__device__ __forceinline__ void conv_k(
    const float* __restrict__ xs, int lane,
    int d, int pd, int ol, float bs,
    const float* __restrict__ wreg, int T,
    float& mx, float& cnt)
{
    for (int r = 0; r < d; r++) {
        if (r >= ol) break;
        const int M = (ol - r + d - 1) / d;       // outputs in this residue
        const int idx0 = r - pd;                  // x index at m=0, j=0
        for (int m0 = 0; m0 < M; m0 += NB) {
            const int base = idx0 + m0 * d;
            const int last = base + (NB + KLEN - 2) * d;
            float Y[NB + KLEN - 1];
            if (base >= 0 && last < T) {          // warp-uniform branch
#pragma unroll
                for (int t = 0; t < NB + KLEN - 1; t++)
                    Y[t] = xs[(base + t * d) * XPITCH + lane];
            } else {
#pragma unroll
                for (int t = 0; t < NB + KLEN - 1; t++) {
                    const int ix = base + t * d;
                    float v = 0.0f;
                    if (ix >= 0 && ix < T) v = xs[ix * XPITCH + lane];
                    Y[t] = v;
                }
            }
#pragma unroll
            for (int i = 0; i < NB; i++) {
                float a = bs;
#pragma unroll
                for (int j = 0; j < KLEN; j++) a = fmaf(wreg[j], Y[i + j], a);
                if (m0 + i < M) {                 // warp-uniform predicate
                    mx = fmaxf(mx, a);
                    cnt += (a > 0.0f) ? 1.0f : 0.0f;
                }
            }
        }
    }
}

__global__ void __launch_bounds__(32 * WARPS_PER_CTA, 3)
rf_kernel(const float* __restrict__ x,
          const float* __restrict__ w,
          const float* __restrict__ bias,
          const int*   __restrict__ dil,
          const int*   __restrict__ padr,
          const int*   __restrict__ olen,
          float* __restrict__ out,
          int B, int T, int K) {
    extern __shared__ float xs[];                 // [T][XPITCH]

    const int lane = threadIdx.x & 31;
    const int warp = threadIdx.x >> 5;
    const int b0   = blockIdx.y * 32;             // batch group base
    const int nb   = min(32, B - b0);

    // Fill xs transposed: coalesced LDG (consecutive t), conflict-free STS.
    for (int i = threadIdx.x; i < 32 * T; i += blockDim.x) {
        const int bb = i / T;
        const int t  = i - bb * T;
        xs[t * XPITCH + bb] =
            (bb < nb) ? x[(size_t)(b0 + bb) * T + t] : 0.0f;
    }
    __syncthreads();

    const int k = blockIdx.x * WARPS_PER_CTA + warp;
    if (k >= K) return;

    const int   d  = dil[k];
    const int   pd = padr[k];
    const int   ol = olen[k];
    const float bs = bias[k];

    float wreg[MAX_KLEN];
#pragma unroll
    for (int j = 0; j < MAX_KLEN; j++) wreg[j] = __ldg(&w[(size_t)k * MAX_KLEN + j]);

    float mx  = -CUDART_INF_F;
    float cnt = 0.0f;

    if (d >= 1) {
        // klen inference: taps >= klen are exactly zero by construction.
        if (wreg[9] != 0.0f || wreg[10] != 0.0f)
            conv_k<11>(xs, lane, d, pd, ol, bs, wreg, T, mx, cnt);
        else if (wreg[7] != 0.0f || wreg[8] != 0.0f)
            conv_k<9>(xs, lane, d, pd, ol, bs, wreg, T, mx, cnt);
        else
            conv_k<7>(xs, lane, d, pd, ol, bs, wreg, T, mx, cnt);
    }

    if (lane < nb) {
        float* o = out + (size_t)(b0 + lane) * 2 * K + 2 * k;
        o[0] = mx;
        o[1] = cnt / (float)ol;
    }
}

extern "C" void kernel_launch(void* const* d_in, const int* in_sizes, int n_in,
                              void* d_out, int out_size) {
    const float* x    = (const float*)d_in[0];
    const float* w    = (const float*)d_in[1];
    const float* bias = (const float*)d_in[2];
    const int*   dil  = (const int*)d_in[3];
    const int*   padr = (const int*)d_in[4];
    const int*   olen = (const int*)d_in[5];
    float* out = (float*)d_out;

    const int K = in_sizes[2];                 // bias element count
    const int B = out_size / (2 * K);
    const int T = in_sizes[0] / B;

    const size_t smem = (size_t)T * XPITCH * sizeof(float);
    cudaFuncSetAttribute(rf_kernel,
                         cudaFuncAttributeMaxDynamicSharedMemorySize,
                         (int)smem);

    dim3 block(32 * WARPS_PER_CTA);
    dim3 grid((K + WARPS_PER_CTA - 1) / WARPS_PER_CTA, (B + 31) / 32);
    rf_kernel<<<grid, block, smem>>>(x, w, bias, dil, padr, olen, out, B, T, K);
}

// round 4
// speedup vs baseline: 1.5983x; 1.5983x over previous
#include <cuda_runtime.h>
#include <math_constants.h>

// RandomFeatures, round 4: persistent warps + dynamic quarter-units.
// lane = batch; xs transposed [T][33] in shared (conflict-free, warp-uniform idx).
// Each work unit = (k, quarter). d>=4: quarter takes residues r = q mod 4 (full
// sliding windows). d<4: quarter takes an m-subrange per residue. Exact 8/4/2/1
// block chain -> no masked FMAs. Partials to device scratch; finalize combines.

#define MAX_KLEN 11
#define WARPS_PER_CTA 10
#define XPITCH 33
#define NQ 4
#define BGMAX 4
#define KMAX 8192

__device__ int   g_ctr[BGMAX];
__device__ float g_scr[(size_t)BGMAX * KMAX * NQ * 64];

__global__ void rf_init() {
    if (threadIdx.x < BGMAX) g_ctr[threadIdx.x] = 0;
}

template<int KLEN, int NB>
__device__ __forceinline__ void conv_block(
    const float* __restrict__ xsl,   // xs + lane
    int base, int d, int dp, int T,
    const float* __restrict__ w, float bs,
    float& mx, float& cnt)
{
    float Y[NB + KLEN - 1];
    const int last = base + (NB + KLEN - 2) * d;
    if (base >= 0 && last < T) {                 // warp-uniform fast path
        const float* p = xsl + base * XPITCH;
#pragma unroll
        for (int t = 0; t < NB + KLEN - 1; t++) Y[t] = p[t * dp];
    } else {
#pragma unroll
        for (int t = 0; t < NB + KLEN - 1; t++) {
            const int ix = base + t * d;
            const int ixc = min(max(ix, 0), T - 1);   // safe address
            float v = xsl[ixc * XPITCH];
            Y[t] = (ix >= 0 && ix < T) ? v : 0.0f;
        }
    }
#pragma unroll
    for (int i = 0; i < NB; i++) {
        float a = bs;
#pragma unroll
        for (int j = 0; j < KLEN; j++) a = fmaf(w[j], Y[i + j], a);
        mx = fmaxf(mx, a);
        cnt += (a > 0.0f) ? 1.0f : 0.0f;
    }
}

template<int KLEN>
__device__ __forceinline__ void conv_range(
    const float* __restrict__ xsl, int r, int pd, int mlo, int mhi,
    int d, int dp, int T, const float* __restrict__ w, float bs,
    float& mx, float& cnt)
{
    int m0 = mlo;
    int base = r - pd + m0 * d;
    for (; m0 + 8 <= mhi; m0 += 8) {
        conv_block<KLEN, 8>(xsl, base, d, dp, T, w, bs, mx, cnt);
        base += 8 * d;
    }
    if (m0 + 4 <= mhi) { conv_block<KLEN, 4>(xsl, base, d, dp, T, w, bs, mx, cnt); m0 += 4; base += 4 * d; }
    if (m0 + 2 <= mhi) { conv_block<KLEN, 2>(xsl, base, d, dp, T, w, bs, mx, cnt); m0 += 2; base += 2 * d; }
    if (m0 < mhi)      { conv_block<KLEN, 1>(xsl, base, d, dp, T, w, bs, mx, cnt); }
}

template<int KLEN>
__device__ __forceinline__ void process_unit(
    const float* __restrict__ xsl, int d, int pd, int ol, int q, int T,
    const float* __restrict__ w, float bs, float& mx, float& cnt)
{
    const int dp = d * XPITCH;
    const int q0 = (ol - 1) / d;                 // single division per unit
    const int rr = (ol - 1) - q0 * d;
    if (d >= NQ) {
        for (int r = q; r < d; r += NQ) {
            const int M = (r <= rr) ? q0 + 1 : q0;   // = ceil((ol-r)/d)
            conv_range<KLEN>(xsl, r, pd, 0, M, d, dp, T, w, bs, mx, cnt);
        }
    } else {
        for (int r = 0; r < d; r++) {
            const int M = (r <= rr) ? q0 + 1 : q0;
            conv_range<KLEN>(xsl, r, pd, (q * M) >> 2, ((q + 1) * M) >> 2,
                             d, dp, T, w, bs, mx, cnt);
        }
    }
}

__global__ void __launch_bounds__(32 * WARPS_PER_CTA, 3)
rf_main(const float* __restrict__ x,
        const float* __restrict__ w,
        const float* __restrict__ bias,
        const int*   __restrict__ dil,
        const int*   __restrict__ padr,
        const int*   __restrict__ olen,
        int B, int T, int K)
{
    extern __shared__ float xs[];                 // [T][XPITCH]
    const int lane = threadIdx.x & 31;
    const int warp = threadIdx.x >> 5;
    const int bg   = blockIdx.y;
    const int b0   = bg * 32;
    const int nb   = min(32, B - b0);

    // Transposed fill: coalesced LDG (consecutive t), conflict-free STS.
    for (int bb = warp; bb < 32; bb += WARPS_PER_CTA) {
        const int bsafe = min(bb, nb - 1);
        for (int t = lane; t < T; t += 32) {
            float v = x[(size_t)(b0 + bsafe) * T + t];
            xs[t * XPITCH + bb] = (bb < nb) ? v : 0.0f;
        }
    }
    __syncthreads();

    const float* xsl = xs + lane;
    const int nunits = K * NQ;

    for (;;) {
        int u = 0;
        if (lane == 0) u = atomicAdd(&g_ctr[bg], 1);
        u = __shfl_sync(0xFFFFFFFFu, u, 0);
        if (u >= nunits) break;

        const int k = u >> 2;
        const int q = u & (NQ - 1);
        const int   d  = dil[k];
        const int   pd = padr[k];
        const int   ol = olen[k];
        const float bv = bias[k];

        float wreg[MAX_KLEN];
#pragma unroll
        for (int j = 0; j < MAX_KLEN; j++)
            wreg[j] = __ldg(&w[(size_t)k * MAX_KLEN + j]);

        float mx  = -CUDART_INF_F;
        float cnt = 0.0f;

        // klen inference: taps >= klen are exactly zero by construction.
        if (wreg[9] != 0.0f || wreg[10] != 0.0f)
            process_unit<11>(xsl, d, pd, ol, q, T, wreg, bv, mx, cnt);
        else if (wreg[7] != 0.0f || wreg[8] != 0.0f)
            process_unit<9>(xsl, d, pd, ol, q, T, wreg, bv, mx, cnt);
        else
            process_unit<7>(xsl, d, pd, ol, q, T, wreg, bv, mx, cnt);

        float* s = g_scr + ((size_t)bg * KMAX * NQ + u) * 64;
        s[lane]      = mx;
        s[32 + lane] = cnt;
    }
}

__global__ void rf_fin(const int* __restrict__ olen,
                       float* __restrict__ out, int B, int K)
{
    const int lane = threadIdx.x;                 // batch within group
    const int k    = blockIdx.x * blockDim.y + threadIdx.y;
    const int bg   = blockIdx.y;
    const int b    = bg * 32 + lane;
    if (k >= K) return;

    const float* s = g_scr + ((size_t)bg * KMAX * NQ + (size_t)k * NQ) * 64;
    float mx  = s[lane];
    float cnt = s[32 + lane];
#pragma unroll
    for (int q = 1; q < NQ; q++) {
        mx   = fmaxf(mx, s[q * 64 + lane]);
        cnt += s[q * 64 + 32 + lane];
    }
    if (b < B) {
        float* o = out + (size_t)b * 2 * K + 2 * k;
        o[0] = mx;
        o[1] = cnt / (float)olen[k];
    }
}

extern "C" void kernel_launch(void* const* d_in, const int* in_sizes, int n_in,
                              void* d_out, int out_size) {
    const float* x    = (const float*)d_in[0];
    const float* w    = (const float*)d_in[1];
    const float* bias = (const float*)d_in[2];
    const int*   dil  = (const int*)d_in[3];
    const int*   padr = (const int*)d_in[4];
    const int*   olen = (const int*)d_in[5];
    float* out = (float*)d_out;

    const int K = in_sizes[2];                 // bias element count
    const int B = out_size / (2 * K);
    const int T = in_sizes[0] / B;
    const int nbg = (B + 31) / 32;             // batch groups (<= BGMAX expected)

    const size_t smem = (size_t)T * XPITCH * sizeof(float);
    cudaFuncSetAttribute(rf_main,
                         cudaFuncAttributeMaxDynamicSharedMemorySize,
                         (int)smem);

    rf_init<<<1, 32>>>();

    // ~3 CTAs/SM x 148 SMs persistent, split across batch groups.
    int ctas_per_bg = (444 + nbg - 1) / nbg;
    dim3 grid(ctas_per_bg, nbg);
    rf_main<<<grid, 32 * WARPS_PER_CTA, smem>>>(x, w, bias, dil, padr, olen,
                                                B, T, K);

    dim3 fblock(32, 8);
    dim3 fgrid((K + 7) / 8, nbg);
    rf_fin<<<fgrid, fblock>>>(olen, out, B, K);
}